// round 9
// baseline (speedup 1.0000x reference)
#include <cuda_runtime.h>
#include <cstdint>

#define B_  2
#define S_  2048
#define D_  1024
#define H_  16
#define HD_ 64
#define M_  (B_*S_)          // 4096 rows for all GEMMs

// Scratch (allocation-free rule: __device__ globals). 48 MB total.
__device__ float g_Q[(size_t)M_*D_];
__device__ float g_K[(size_t)M_*D_];
__device__ float g_V[(size_t)M_*D_];
__device__ float g_ctx[(size_t)M_*D_];

// ---------------------------------------------------------------------------
// GEMM: C[M_,1024] = A[M_,1024] @ W[1024,1024] + bias, fp32.
// 128x128 block tile, BK=16, 256 threads, 8x8 per-thread microtile.
// ---------------------------------------------------------------------------
__global__ __launch_bounds__(256)
void gemm_bias_128x128(const float* __restrict__ A, const float* __restrict__ W,
                       const float* __restrict__ bias, float* __restrict__ C)
{
    const int K = D_, N = D_;
    __shared__ float As[16][128];   // transposed A tile: As[k][m]
    __shared__ float Bs[16][128];   // Bs[k][n]

    const int tid = threadIdx.x;
    const int tx  = tid & 15;       // -> 2 groups of 4 output cols
    const int ty  = tid >> 4;       // -> 2 groups of 4 output rows
    const int rowBase = blockIdx.y * 128;
    const int colBase = blockIdx.x * 128;

    const float* Ap = A + (size_t)rowBase * K;
    const float* Wp = W + colBase;

    float acc[8][8];
#pragma unroll
    for (int i = 0; i < 8; i++)
#pragma unroll
        for (int j = 0; j < 8; j++) acc[i][j] = 0.f;

    for (int kt = 0; kt < K; kt += 16) {
        // Load A tile 128x16 as float4, store transposed.
#pragma unroll
        for (int v = tid; v < 512; v += 256) {
            int r = v >> 2, c4 = v & 3;
            float4 a = *reinterpret_cast<const float4*>(Ap + (size_t)r * K + kt + c4 * 4);
            As[c4*4+0][r] = a.x; As[c4*4+1][r] = a.y;
            As[c4*4+2][r] = a.z; As[c4*4+3][r] = a.w;
        }
        // Load W tile 16x128 as float4.
#pragma unroll
        for (int v = tid; v < 512; v += 256) {
            int r = v >> 5, c4 = v & 31;
            *reinterpret_cast<float4*>(&Bs[r][c4*4]) =
                *reinterpret_cast<const float4*>(Wp + (size_t)(kt + r) * N + c4 * 4);
        }
        __syncthreads();

#pragma unroll
        for (int kk = 0; kk < 16; kk++) {
            float a[8], b[8];
#pragma unroll
            for (int i = 0; i < 4; i++) {
                a[i]     = As[kk][ty*4 + i];
                a[i + 4] = As[kk][64 + ty*4 + i];
            }
#pragma unroll
            for (int j = 0; j < 4; j++) {
                b[j]     = Bs[kk][tx*4 + j];
                b[j + 4] = Bs[kk][64 + tx*4 + j];
            }
#pragma unroll
            for (int i = 0; i < 8; i++)
#pragma unroll
                for (int j = 0; j < 8; j++)
                    acc[i][j] = fmaf(a[i], b[j], acc[i][j]);
        }
        __syncthreads();
    }

#pragma unroll
    for (int i = 0; i < 8; i++) {
        int r = rowBase + ((i < 4) ? (ty*4 + i) : (64 + ty*4 + i - 4));
#pragma unroll
        for (int jg = 0; jg < 2; jg++) {
            int c = colBase + (jg ? (64 + tx*4) : (tx*4));
            float4 o;
            o.x = acc[i][jg*4+0] + bias[c+0];
            o.y = acc[i][jg*4+1] + bias[c+1];
            o.z = acc[i][jg*4+2] + bias[c+2];
            o.w = acc[i][jg*4+3] + bias[c+3];
            *reinterpret_cast<float4*>(C + (size_t)r * N + c) = o;
        }
    }
}

// ---------------------------------------------------------------------------
// Flash attention per (b,h,q-tile of 64), K-tiles of 64, online softmax.
// ctx = (1-beta) * softmax(QK^T/8) @ V + beta * (ds @ V)    [ds term folded in]
// 256 threads; each thread owns a 4x4 output microtile.
// ---------------------------------------------------------------------------
#define SSTR 65   // smem row stride (65 = conflict-free for strided row reads)
#define FLASH_SMEM ((4*64*SSTR + 4*64) * sizeof(float))   // 67584 bytes

__global__ __launch_bounds__(256)
void flash_kernel(const float* __restrict__ Qg, const float* __restrict__ Kg,
                  const float* __restrict__ Vg, const float* __restrict__ dsg,
                  const float* __restrict__ betap, float* __restrict__ ctx)
{
    extern __shared__ float sm[];
    float* Qs     = sm;                  // 64 x SSTR
    float* Ks     = Qs + 64*SSTR;        // 64 x SSTR
    float* Vs     = Ks + 64*SSTR;        // 64 x SSTR
    float* Ps     = Vs + 64*SSTR;        // 64 x SSTR  (scores -> probs)
    float* m_s    = Ps + 64*SSTR;        // 64 running max
    float* l_s    = m_s + 64;            // 64 running sum
    float* corr_s = l_s + 64;            // 64 rescale factors
    float* ds_s   = corr_s + 64;         // 64 docking scores for this k-tile

    const int bh = blockIdx.y;
    const int b  = bh >> 4;              // / H_
    const int h  = bh & 15;
    const int q0 = blockIdx.x * 64;
    const int tid = threadIdx.x;
    const int tx = tid & 15;             // 4 output cols
    const int ty = tid >> 4;             // 4 output rows

    const float* Qb = Qg + ((size_t)(b*S_ + q0)) * D_ + h*HD_;
    const float* Kb = Kg + ((size_t)b * S_) * D_ + h*HD_;
    const float* Vb = Vg + ((size_t)b * S_) * D_ + h*HD_;

    // Load Q tile [64 x 64]
    for (int idx = tid; idx < 4096; idx += 256) {
        int r = idx >> 6, c = idx & 63;
        Qs[r*SSTR + c] = Qb[(size_t)r * D_ + c];
    }
    if (tid < 64) { m_s[tid] = -1e30f; l_s[tid] = 0.f; }

    float O[4][4], dsacc[4];
#pragma unroll
    for (int i = 0; i < 4; i++) {
        dsacc[i] = 0.f;
#pragma unroll
        for (int j = 0; j < 4; j++) O[i][j] = 0.f;
    }

    for (int kt = 0; kt < S_; kt += 64) {
        __syncthreads();   // protect Ks/Vs/Ps from previous iteration's readers
        for (int idx = tid; idx < 4096; idx += 256) {
            int r = idx >> 6, c = idx & 63;
            Ks[r*SSTR + c] = Kb[(size_t)(kt + r) * D_ + c];
            Vs[r*SSTR + c] = Vb[(size_t)(kt + r) * D_ + c];
        }
        if (tid < 64) ds_s[tid] = dsg[b*S_ + kt + tid];
        __syncthreads();

        // S = (Q @ K^T) * 1/sqrt(64)
        float s[4][4];
#pragma unroll
        for (int i = 0; i < 4; i++)
#pragma unroll
            for (int j = 0; j < 4; j++) s[i][j] = 0.f;

#pragma unroll
        for (int d = 0; d < 64; d++) {
            float a0 = Qs[(ty*4+0)*SSTR + d];
            float a1 = Qs[(ty*4+1)*SSTR + d];
            float a2 = Qs[(ty*4+2)*SSTR + d];
            float a3 = Qs[(ty*4+3)*SSTR + d];
            float b0 = Ks[(tx*4+0)*SSTR + d];
            float b1 = Ks[(tx*4+1)*SSTR + d];
            float b2 = Ks[(tx*4+2)*SSTR + d];
            float b3 = Ks[(tx*4+3)*SSTR + d];
            s[0][0] = fmaf(a0,b0,s[0][0]); s[0][1] = fmaf(a0,b1,s[0][1]);
            s[0][2] = fmaf(a0,b2,s[0][2]); s[0][3] = fmaf(a0,b3,s[0][3]);
            s[1][0] = fmaf(a1,b0,s[1][0]); s[1][1] = fmaf(a1,b1,s[1][1]);
            s[1][2] = fmaf(a1,b2,s[1][2]); s[1][3] = fmaf(a1,b3,s[1][3]);
            s[2][0] = fmaf(a2,b0,s[2][0]); s[2][1] = fmaf(a2,b1,s[2][1]);
            s[2][2] = fmaf(a2,b2,s[2][2]); s[2][3] = fmaf(a2,b3,s[2][3]);
            s[3][0] = fmaf(a3,b0,s[3][0]); s[3][1] = fmaf(a3,b1,s[3][1]);
            s[3][2] = fmaf(a3,b2,s[3][2]); s[3][3] = fmaf(a3,b3,s[3][3]);
        }
#pragma unroll
        for (int i = 0; i < 4; i++)
#pragma unroll
            for (int j = 0; j < 4; j++)
                Ps[(ty*4+i)*SSTR + tx*4 + j] = s[i][j] * 0.125f;
        __syncthreads();

        // Row stats: tile max -> new running max + correction factor
        if (tid < 64) {
            const float* row = Ps + tid*SSTR;
            float tm = row[0];
            for (int k2 = 1; k2 < 64; k2++) tm = fmaxf(tm, row[k2]);
            float mo = m_s[tid];
            float mn = fmaxf(mo, tm);
            corr_s[tid] = __expf(mo - mn);
            m_s[tid] = mn;
        }
        __syncthreads();

        // Rescale accumulators, exponentiate scores in place
#pragma unroll
        for (int i = 0; i < 4; i++) {
            float c = corr_s[ty*4 + i];
#pragma unroll
            for (int j = 0; j < 4; j++) O[i][j] *= c;
        }
        for (int idx = tid; idx < 4096; idx += 256) {
            int r = idx >> 6, c = idx & 63;
            Ps[r*SSTR + c] = __expf(Ps[r*SSTR + c] - m_s[r]);
        }
        __syncthreads();

        // Row sums update (64 threads) runs alongside P @ V (all threads)
        if (tid < 64) {
            const float* row = Ps + tid*SSTR;
            float rs = 0.f;
            for (int k2 = 0; k2 < 64; k2++) rs += row[k2];
            l_s[tid] = l_s[tid]*corr_s[tid] + rs;
        }

        // O += P @ V ; dsacc += ds @ V (docking rank-1 term, V already in smem)
#pragma unroll
        for (int k2 = 0; k2 < 64; k2++) {
            float p0 = Ps[(ty*4+0)*SSTR + k2];
            float p1 = Ps[(ty*4+1)*SSTR + k2];
            float p2 = Ps[(ty*4+2)*SSTR + k2];
            float p3 = Ps[(ty*4+3)*SSTR + k2];
            float v0 = Vs[k2*SSTR + tx*4 + 0];
            float v1 = Vs[k2*SSTR + tx*4 + 1];
            float v2 = Vs[k2*SSTR + tx*4 + 2];
            float v3 = Vs[k2*SSTR + tx*4 + 3];
            float dw = ds_s[k2];
            O[0][0] = fmaf(p0,v0,O[0][0]); O[0][1] = fmaf(p0,v1,O[0][1]);
            O[0][2] = fmaf(p0,v2,O[0][2]); O[0][3] = fmaf(p0,v3,O[0][3]);
            O[1][0] = fmaf(p1,v0,O[1][0]); O[1][1] = fmaf(p1,v1,O[1][1]);
            O[1][2] = fmaf(p1,v2,O[1][2]); O[1][3] = fmaf(p1,v3,O[1][3]);
            O[2][0] = fmaf(p2,v0,O[2][0]); O[2][1] = fmaf(p2,v1,O[2][1]);
            O[2][2] = fmaf(p2,v2,O[2][2]); O[2][3] = fmaf(p2,v3,O[2][3]);
            O[3][0] = fmaf(p3,v0,O[3][0]); O[3][1] = fmaf(p3,v1,O[3][1]);
            O[3][2] = fmaf(p3,v2,O[3][2]); O[3][3] = fmaf(p3,v3,O[3][3]);
            dsacc[0] = fmaf(dw,v0,dsacc[0]); dsacc[1] = fmaf(dw,v1,dsacc[1]);
            dsacc[2] = fmaf(dw,v2,dsacc[2]); dsacc[3] = fmaf(dw,v3,dsacc[3]);
        }
    }
    __syncthreads();   // final l_s visible

    const float bv  = *betap;
    const float omb = 1.f - bv;
#pragma unroll
    for (int i = 0; i < 4; i++) {
        int r = ty*4 + i;
        float invl = 1.f / l_s[r];
        float4 o;
        o.x = omb * O[i][0] * invl + bv * dsacc[0];
        o.y = omb * O[i][1] * invl + bv * dsacc[1];
        o.z = omb * O[i][2] * invl + bv * dsacc[2];
        o.w = omb * O[i][3] * invl + bv * dsacc[3];
        *reinterpret_cast<float4*>(ctx + ((size_t)(b*S_ + q0 + r)) * D_ + h*HD_ + tx*4) = o;
    }
}

// ---------------------------------------------------------------------------
extern "C" void kernel_launch(void* const* d_in, const int* in_sizes, int n_in,
                              void* d_out, int out_size)
{
    (void)in_sizes; (void)n_in; (void)out_size;
    const float* x    = (const float*)d_in[0];
    const float* ds   = (const float*)d_in[1];
    const float* Wq   = (const float*)d_in[2];
    const float* bq   = (const float*)d_in[3];
    const float* Wk   = (const float*)d_in[4];
    const float* bk   = (const float*)d_in[5];
    const float* Wv   = (const float*)d_in[6];
    const float* bv   = (const float*)d_in[7];
    const float* Wo   = (const float*)d_in[8];
    const float* bo   = (const float*)d_in[9];
    const float* beta = (const float*)d_in[10];
    float* out = (float*)d_out;

    float *Qp, *Kp, *Vp, *Cp;
    cudaGetSymbolAddress((void**)&Qp, g_Q);
    cudaGetSymbolAddress((void**)&Kp, g_K);
    cudaGetSymbolAddress((void**)&Vp, g_V);
    cudaGetSymbolAddress((void**)&Cp, g_ctx);

    cudaFuncSetAttribute(flash_kernel, cudaFuncAttributeMaxDynamicSharedMemorySize,
                         (int)FLASH_SMEM);

    dim3 ggrid(D_/128, M_/128);   // (8, 32)
    gemm_bias_128x128<<<ggrid, 256>>>(x, Wq, bq, Qp);
    gemm_bias_128x128<<<ggrid, 256>>>(x, Wk, bk, Kp);
    gemm_bias_128x128<<<ggrid, 256>>>(x, Wv, bv, Vp);
    flash_kernel<<<dim3(S_/64, B_*H_), 256, FLASH_SMEM>>>(Qp, Kp, Vp, ds, beta, Cp);
    gemm_bias_128x128<<<ggrid, 256>>>(Cp, Wo, bo, out);
}

// round 10
// speedup vs baseline: 1.0011x; 1.0011x over previous
#include <cuda_runtime.h>
#include <cstdint>

#define B_  2
#define S_  2048
#define D_  1024
#define H_  16
#define HD_ 64
#define M_  (B_*S_)          // 4096 rows for all GEMMs

// Scratch (allocation-free rule: __device__ globals). 48 MB total.
__device__ float g_Q[(size_t)M_*D_];
__device__ float g_K[(size_t)M_*D_];
__device__ float g_V[(size_t)M_*D_];
__device__ float g_ctx[(size_t)M_*D_];

// ---------------------------------------------------------------------------
// GEMM: C[M_,1024] = A[M_,1024] @ W[1024,1024] + bias, fp32.
// 128x128 block tile, BK=16, 256 threads, 8x8 per-thread microtile.
// ---------------------------------------------------------------------------
__global__ __launch_bounds__(256)
void gemm_bias_128x128(const float* __restrict__ A, const float* __restrict__ W,
                       const float* __restrict__ bias, float* __restrict__ C)
{
    const int K = D_, N = D_;
    __shared__ float As[16][128];   // transposed A tile: As[k][m]
    __shared__ float Bs[16][128];   // Bs[k][n]

    const int tid = threadIdx.x;
    const int tx  = tid & 15;       // -> 2 groups of 4 output cols
    const int ty  = tid >> 4;       // -> 2 groups of 4 output rows
    const int rowBase = blockIdx.y * 128;
    const int colBase = blockIdx.x * 128;

    const float* Ap = A + (size_t)rowBase * K;
    const float* Wp = W + colBase;

    float acc[8][8];
#pragma unroll
    for (int i = 0; i < 8; i++)
#pragma unroll
        for (int j = 0; j < 8; j++) acc[i][j] = 0.f;

    for (int kt = 0; kt < K; kt += 16) {
        // Load A tile 128x16 as float4, store transposed.
#pragma unroll
        for (int v = tid; v < 512; v += 256) {
            int r = v >> 2, c4 = v & 3;
            float4 a = *reinterpret_cast<const float4*>(Ap + (size_t)r * K + kt + c4 * 4);
            As[c4*4+0][r] = a.x; As[c4*4+1][r] = a.y;
            As[c4*4+2][r] = a.z; As[c4*4+3][r] = a.w;
        }
        // Load W tile 16x128 as float4.
#pragma unroll
        for (int v = tid; v < 512; v += 256) {
            int r = v >> 5, c4 = v & 31;
            *reinterpret_cast<float4*>(&Bs[r][c4*4]) =
                *reinterpret_cast<const float4*>(Wp + (size_t)(kt + r) * N + c4 * 4);
        }
        __syncthreads();

#pragma unroll
        for (int kk = 0; kk < 16; kk++) {
            float a[8], b[8];
#pragma unroll
            for (int i = 0; i < 4; i++) {
                a[i]     = As[kk][ty*4 + i];
                a[i + 4] = As[kk][64 + ty*4 + i];
            }
#pragma unroll
            for (int j = 0; j < 4; j++) {
                b[j]     = Bs[kk][tx*4 + j];
                b[j + 4] = Bs[kk][64 + tx*4 + j];
            }
#pragma unroll
            for (int i = 0; i < 8; i++)
#pragma unroll
                for (int j = 0; j < 8; j++)
                    acc[i][j] = fmaf(a[i], b[j], acc[i][j]);
        }
        __syncthreads();
    }

#pragma unroll
    for (int i = 0; i < 8; i++) {
        int r = rowBase + ((i < 4) ? (ty*4 + i) : (64 + ty*4 + i - 4));
#pragma unroll
        for (int jg = 0; jg < 2; jg++) {
            int c = colBase + (jg ? (64 + tx*4) : (tx*4));
            float4 o;
            o.x = acc[i][jg*4+0] + bias[c+0];
            o.y = acc[i][jg*4+1] + bias[c+1];
            o.z = acc[i][jg*4+2] + bias[c+2];
            o.w = acc[i][jg*4+3] + bias[c+3];
            *reinterpret_cast<float4*>(C + (size_t)r * N + c) = o;
        }
    }
}

// ---------------------------------------------------------------------------
// Flash attention per (b,h,q-tile of 64), K-tiles of 64, online softmax.
// ctx = (1-beta) * softmax(QK^T/8) @ V + beta * (ds @ V)    [ds term folded in]
// 256 threads; each thread owns a 4x4 output microtile.
// ---------------------------------------------------------------------------
#define SSTR 65   // smem row stride (65 = conflict-free for strided row reads)
#define FLASH_SMEM ((4*64*SSTR + 4*64) * sizeof(float))   // 67584 bytes

__global__ __launch_bounds__(256)
void flash_kernel(const float* __restrict__ Qg, const float* __restrict__ Kg,
                  const float* __restrict__ Vg, const float* __restrict__ dsg,
                  const float* __restrict__ betap, float* __restrict__ ctx)
{
    extern __shared__ float sm[];
    float* Qs     = sm;                  // 64 x SSTR
    float* Ks     = Qs + 64*SSTR;        // 64 x SSTR
    float* Vs     = Ks + 64*SSTR;        // 64 x SSTR
    float* Ps     = Vs + 64*SSTR;        // 64 x SSTR  (scores -> probs)
    float* m_s    = Ps + 64*SSTR;        // 64 running max
    float* l_s    = m_s + 64;            // 64 running sum
    float* corr_s = l_s + 64;            // 64 rescale factors
    float* ds_s   = corr_s + 64;         // 64 docking scores for this k-tile

    const int bh = blockIdx.y;
    const int b  = bh >> 4;              // / H_
    const int h  = bh & 15;
    const int q0 = blockIdx.x * 64;
    const int tid = threadIdx.x;
    const int tx = tid & 15;             // 4 output cols
    const int ty = tid >> 4;             // 4 output rows

    const float* Qb = Qg + ((size_t)(b*S_ + q0)) * D_ + h*HD_;
    const float* Kb = Kg + ((size_t)b * S_) * D_ + h*HD_;
    const float* Vb = Vg + ((size_t)b * S_) * D_ + h*HD_;

    // Load Q tile [64 x 64]
    for (int idx = tid; idx < 4096; idx += 256) {
        int r = idx >> 6, c = idx & 63;
        Qs[r*SSTR + c] = Qb[(size_t)r * D_ + c];
    }
    if (tid < 64) { m_s[tid] = -1e30f; l_s[tid] = 0.f; }

    float O[4][4], dsacc[4];
#pragma unroll
    for (int i = 0; i < 4; i++) {
        dsacc[i] = 0.f;
#pragma unroll
        for (int j = 0; j < 4; j++) O[i][j] = 0.f;
    }

    for (int kt = 0; kt < S_; kt += 64) {
        __syncthreads();   // protect Ks/Vs/Ps from previous iteration's readers
        for (int idx = tid; idx < 4096; idx += 256) {
            int r = idx >> 6, c = idx & 63;
            Ks[r*SSTR + c] = Kb[(size_t)(kt + r) * D_ + c];
            Vs[r*SSTR + c] = Vb[(size_t)(kt + r) * D_ + c];
        }
        if (tid < 64) ds_s[tid] = dsg[b*S_ + kt + tid];
        __syncthreads();

        // S = (Q @ K^T) * 1/sqrt(64)
        float s[4][4];
#pragma unroll
        for (int i = 0; i < 4; i++)
#pragma unroll
            for (int j = 0; j < 4; j++) s[i][j] = 0.f;

#pragma unroll
        for (int d = 0; d < 64; d++) {
            float a0 = Qs[(ty*4+0)*SSTR + d];
            float a1 = Qs[(ty*4+1)*SSTR + d];
            float a2 = Qs[(ty*4+2)*SSTR + d];
            float a3 = Qs[(ty*4+3)*SSTR + d];
            float b0 = Ks[(tx*4+0)*SSTR + d];
            float b1 = Ks[(tx*4+1)*SSTR + d];
            float b2 = Ks[(tx*4+2)*SSTR + d];
            float b3 = Ks[(tx*4+3)*SSTR + d];
            s[0][0] = fmaf(a0,b0,s[0][0]); s[0][1] = fmaf(a0,b1,s[0][1]);
            s[0][2] = fmaf(a0,b2,s[0][2]); s[0][3] = fmaf(a0,b3,s[0][3]);
            s[1][0] = fmaf(a1,b0,s[1][0]); s[1][1] = fmaf(a1,b1,s[1][1]);
            s[1][2] = fmaf(a1,b2,s[1][2]); s[1][3] = fmaf(a1,b3,s[1][3]);
            s[2][0] = fmaf(a2,b0,s[2][0]); s[2][1] = fmaf(a2,b1,s[2][1]);
            s[2][2] = fmaf(a2,b2,s[2][2]); s[2][3] = fmaf(a2,b3,s[2][3]);
            s[3][0] = fmaf(a3,b0,s[3][0]); s[3][1] = fmaf(a3,b1,s[3][1]);
            s[3][2] = fmaf(a3,b2,s[3][2]); s[3][3] = fmaf(a3,b3,s[3][3]);
        }
#pragma unroll
        for (int i = 0; i < 4; i++)
#pragma unroll
            for (int j = 0; j < 4; j++)
                Ps[(ty*4+i)*SSTR + tx*4 + j] = s[i][j] * 0.125f;
        __syncthreads();

        // Row stats: tile max -> new running max + correction factor
        if (tid < 64) {
            const float* row = Ps + tid*SSTR;
            float tm = row[0];
            for (int k2 = 1; k2 < 64; k2++) tm = fmaxf(tm, row[k2]);
            float mo = m_s[tid];
            float mn = fmaxf(mo, tm);
            corr_s[tid] = __expf(mo - mn);
            m_s[tid] = mn;
        }
        __syncthreads();

        // Rescale accumulators, exponentiate scores in place
#pragma unroll
        for (int i = 0; i < 4; i++) {
            float c = corr_s[ty*4 + i];
#pragma unroll
            for (int j = 0; j < 4; j++) O[i][j] *= c;
        }
        for (int idx = tid; idx < 4096; idx += 256) {
            int r = idx >> 6, c = idx & 63;
            Ps[r*SSTR + c] = __expf(Ps[r*SSTR + c] - m_s[r]);
        }
        __syncthreads();

        // Row sums update (64 threads) runs alongside P @ V (all threads)
        if (tid < 64) {
            const float* row = Ps + tid*SSTR;
            float rs = 0.f;
            for (int k2 = 0; k2 < 64; k2++) rs += row[k2];
            l_s[tid] = l_s[tid]*corr_s[tid] + rs;
        }

        // O += P @ V ; dsacc += ds @ V (docking rank-1 term, V already in smem)
#pragma unroll
        for (int k2 = 0; k2 < 64; k2++) {
            float p0 = Ps[(ty*4+0)*SSTR + k2];
            float p1 = Ps[(ty*4+1)*SSTR + k2];
            float p2 = Ps[(ty*4+2)*SSTR + k2];
            float p3 = Ps[(ty*4+3)*SSTR + k2];
            float v0 = Vs[k2*SSTR + tx*4 + 0];
            float v1 = Vs[k2*SSTR + tx*4 + 1];
            float v2 = Vs[k2*SSTR + tx*4 + 2];
            float v3 = Vs[k2*SSTR + tx*4 + 3];
            float dw = ds_s[k2];
            O[0][0] = fmaf(p0,v0,O[0][0]); O[0][1] = fmaf(p0,v1,O[0][1]);
            O[0][2] = fmaf(p0,v2,O[0][2]); O[0][3] = fmaf(p0,v3,O[0][3]);
            O[1][0] = fmaf(p1,v0,O[1][0]); O[1][1] = fmaf(p1,v1,O[1][1]);
            O[1][2] = fmaf(p1,v2,O[1][2]); O[1][3] = fmaf(p1,v3,O[1][3]);
            O[2][0] = fmaf(p2,v0,O[2][0]); O[2][1] = fmaf(p2,v1,O[2][1]);
            O[2][2] = fmaf(p2,v2,O[2][2]); O[2][3] = fmaf(p2,v3,O[2][3]);
            O[3][0] = fmaf(p3,v0,O[3][0]); O[3][1] = fmaf(p3,v1,O[3][1]);
            O[3][2] = fmaf(p3,v2,O[3][2]); O[3][3] = fmaf(p3,v3,O[3][3]);
            dsacc[0] = fmaf(dw,v0,dsacc[0]); dsacc[1] = fmaf(dw,v1,dsacc[1]);
            dsacc[2] = fmaf(dw,v2,dsacc[2]); dsacc[3] = fmaf(dw,v3,dsacc[3]);
        }
    }
    __syncthreads();   // final l_s visible

    const float bv  = *betap;
    const float omb = 1.f - bv;
#pragma unroll
    for (int i = 0; i < 4; i++) {
        int r = ty*4 + i;
        float invl = 1.f / l_s[r];
        float4 o;
        o.x = omb * O[i][0] * invl + bv * dsacc[0];
        o.y = omb * O[i][1] * invl + bv * dsacc[1];
        o.z = omb * O[i][2] * invl + bv * dsacc[2];
        o.w = omb * O[i][3] * invl + bv * dsacc[3];
        *reinterpret_cast<float4*>(ctx + ((size_t)(b*S_ + q0 + r)) * D_ + h*HD_ + tx*4) = o;
    }
}

// ---------------------------------------------------------------------------
extern "C" void kernel_launch(void* const* d_in, const int* in_sizes, int n_in,
                              void* d_out, int out_size)
{
    (void)in_sizes; (void)n_in; (void)out_size;
    const float* x    = (const float*)d_in[0];
    const float* ds   = (const float*)d_in[1];
    const float* Wq   = (const float*)d_in[2];
    const float* bq   = (const float*)d_in[3];
    const float* Wk   = (const float*)d_in[4];
    const float* bk   = (const float*)d_in[5];
    const float* Wv   = (const float*)d_in[6];
    const float* bv   = (const float*)d_in[7];
    const float* Wo   = (const float*)d_in[8];
    const float* bo   = (const float*)d_in[9];
    const float* beta = (const float*)d_in[10];
    float* out = (float*)d_out;

    float *Qp, *Kp, *Vp, *Cp;
    cudaGetSymbolAddress((void**)&Qp, g_Q);
    cudaGetSymbolAddress((void**)&Kp, g_K);
    cudaGetSymbolAddress((void**)&Vp, g_V);
    cudaGetSymbolAddress((void**)&Cp, g_ctx);

    cudaFuncSetAttribute(flash_kernel, cudaFuncAttributeMaxDynamicSharedMemorySize,
                         (int)FLASH_SMEM);

    dim3 ggrid(D_/128, M_/128);   // (8, 32)
    gemm_bias_128x128<<<ggrid, 256>>>(x, Wq, bq, Qp);
    gemm_bias_128x128<<<ggrid, 256>>>(x, Wk, bk, Kp);
    gemm_bias_128x128<<<ggrid, 256>>>(x, Wv, bv, Vp);
    flash_kernel<<<dim3(S_/64, B_*H_), 256, FLASH_SMEM>>>(Qp, Kp, Vp, ds, beta, Cp);
    gemm_bias_128x128<<<ggrid, 256>>>(Cp, Wo, bo, out);
}

// round 12
// speedup vs baseline: 1.2201x; 1.2188x over previous
#include <cuda_runtime.h>
#include <cuda_bf16.h>
#include <cstdint>

#define B_  2
#define S_  2048
#define D_  1024
#define H_  16
#define HD_ 64
#define M_  (B_*S_)          // 4096 rows for all GEMMs

// ---------------------------------------------------------------------------
// Scratch (allocation-free rule: __device__ globals).
// ---------------------------------------------------------------------------
__device__ float g_Q[(size_t)M_*D_];
__device__ float g_K[(size_t)M_*D_];
__device__ float g_V[(size_t)M_*D_];
__device__ float g_ctx[(size_t)M_*D_];

__device__ __nv_bfloat16 g_Xh[(size_t)M_*D_];     // x split hi
__device__ __nv_bfloat16 g_Xl[(size_t)M_*D_];     // x split lo
__device__ __nv_bfloat16 g_Ch[(size_t)M_*D_];     // ctx split hi
__device__ __nv_bfloat16 g_Cl[(size_t)M_*D_];     // ctx split lo
__device__ __nv_bfloat16 g_Wth[4][(size_t)D_*D_]; // W^T hi  ([n][k] K-major)
__device__ __nv_bfloat16 g_Wtl[4][(size_t)D_*D_]; // W^T lo

// ---------------------------------------------------------------------------
// Convert kernels
// ---------------------------------------------------------------------------
__global__ __launch_bounds__(256)
void split_rows(const float* __restrict__ X,
                __nv_bfloat16* __restrict__ Xh, __nv_bfloat16* __restrict__ Xl)
{
    size_t i = ((size_t)blockIdx.x * 256 + threadIdx.x) * 4;
    float4 v = *reinterpret_cast<const float4*>(X + i);
    float f[4] = {v.x, v.y, v.z, v.w};
    alignas(8) __nv_bfloat16 h[4];
    alignas(8) __nv_bfloat16 l[4];
#pragma unroll
    for (int j = 0; j < 4; j++) {
        h[j] = __float2bfloat16(f[j]);
        l[j] = __float2bfloat16(f[j] - __bfloat162float(h[j]));
    }
    *reinterpret_cast<uint2*>(Xh + i) = *reinterpret_cast<const uint2*>(h);
    *reinterpret_cast<uint2*>(Xl + i) = *reinterpret_cast<const uint2*>(l);
}

// W [K][N] fp32 -> Wt_hi/lo [N][K] bf16 (K-major: the mma.sync "col" operand)
__global__ __launch_bounds__(256)
void transpose_split(const float* __restrict__ W,
                     __nv_bfloat16* __restrict__ Th, __nv_bfloat16* __restrict__ Tl)
{
    __shared__ float t[32][33];
    const int bx = blockIdx.x * 32;   // n base
    const int by = blockIdx.y * 32;   // k base
    const int tx = threadIdx.x, ty = threadIdx.y;
#pragma unroll
    for (int i = 0; i < 32; i += 8)
        t[ty + i][tx] = W[(size_t)(by + ty + i) * D_ + bx + tx];
    __syncthreads();
#pragma unroll
    for (int i = 0; i < 32; i += 8) {
        float v = t[tx][ty + i];   // = W[by+tx][bx+ty+i]
        __nv_bfloat16 h = __float2bfloat16(v);
        float lo = v - __bfloat162float(h);
        size_t o = (size_t)(bx + ty + i) * D_ + by + tx;   // Wt[n][k]
        Th[o] = h;
        Tl[o] = __float2bfloat16(lo);
    }
}

// ---------------------------------------------------------------------------
// mma.sync split-bf16 GEMM: C[M_,1024] = A@W + bias (fp32-accurate).
// A as (Ahi, Alo) bf16 row-major [M][K]; W as (Bhi, Blo) bf16 [N][K].
// Three K=1024 passes: hi*hi + hi*lo + lo*hi, accumulated in fp32 regs.
// CTA tile 128x128, BK=32, 8 warps (2x4), warp tile 64x32, double-buffered.
// ---------------------------------------------------------------------------
#define BK_   32
#define LDS_  40   // padded smem row length in bf16 (80 B -> conflict-free frags)

__device__ __forceinline__ void mma16816(float* d, const uint32_t* a, const uint32_t* b)
{
    asm volatile(
        "mma.sync.aligned.m16n8k16.row.col.f32.bf16.bf16.f32 "
        "{%0,%1,%2,%3}, {%4,%5,%6,%7}, {%8,%9}, {%0,%1,%2,%3};"
        : "+f"(d[0]), "+f"(d[1]), "+f"(d[2]), "+f"(d[3])
        : "r"(a[0]), "r"(a[1]), "r"(a[2]), "r"(a[3]), "r"(b[0]), "r"(b[1]));
}

__global__ __launch_bounds__(256)
void gemm_mma(const __nv_bfloat16* __restrict__ Ahi, const __nv_bfloat16* __restrict__ Alo,
              const __nv_bfloat16* __restrict__ Bhi, const __nv_bfloat16* __restrict__ Blo,
              const float* __restrict__ bias, float* __restrict__ C)
{
    __shared__ __align__(16) __nv_bfloat16 As[2][128 * LDS_];
    __shared__ __align__(16) __nv_bfloat16 Bs[2][128 * LDS_];

    const int tid  = threadIdx.x;
    const int lane = tid & 31, wid = tid >> 5;
    const int wm   = wid >> 2, wn = wid & 3;       // warp grid 2(M) x 4(N)
    const int m0   = blockIdx.y * 128, n0 = blockIdx.x * 128;
    const int r    = lane >> 2;                    // 0..7 (frag row / n offset)
    const int kq   = (lane & 3) * 2;               // 0,2,4,6 (frag k / out col)
    const int lrow = tid >> 2, lq = tid & 3;       // gmem->smem load mapping

    float acc[4][4][4];
#pragma unroll
    for (int i = 0; i < 4; i++)
#pragma unroll
        for (int j = 0; j < 4; j++)
#pragma unroll
            for (int c = 0; c < 4; c++) acc[i][j][c] = 0.f;

    const int NC = 96;                             // 3 segments x 32 chunks
    uint4 stA0, stA1, stB0, stB1;

    // --- stage chunk cg's tiles into registers ---
#define GLOAD(cg) do {                                                         \
    int _seg = (cg) >> 5;                                                      \
    int _kc  = ((cg) & 31) * BK_;                                              \
    const __nv_bfloat16* _Ag = (_seg == 2 ? Alo : Ahi) + (size_t)m0 * D_ + _kc;\
    const __nv_bfloat16* _Bg = (_seg == 1 ? Blo : Bhi) + (size_t)n0 * D_ + _kc;\
    stA0 = *reinterpret_cast<const uint4*>(_Ag + (size_t)lrow * D_ + lq * 8);  \
    stA1 = *reinterpret_cast<const uint4*>(_Ag + (size_t)(64 + lrow) * D_ + lq * 8); \
    stB0 = *reinterpret_cast<const uint4*>(_Bg + (size_t)lrow * D_ + lq * 8);  \
    stB1 = *reinterpret_cast<const uint4*>(_Bg + (size_t)(64 + lrow) * D_ + lq * 8); \
} while (0)

#define SSTORE(b) do {                                                         \
    *reinterpret_cast<uint4*>(&As[b][lrow * LDS_ + lq * 8])        = stA0;     \
    *reinterpret_cast<uint4*>(&As[b][(64 + lrow) * LDS_ + lq * 8]) = stA1;     \
    *reinterpret_cast<uint4*>(&Bs[b][lrow * LDS_ + lq * 8])        = stB0;     \
    *reinterpret_cast<uint4*>(&Bs[b][(64 + lrow) * LDS_ + lq * 8]) = stB1;     \
} while (0)

    GLOAD(0);
    SSTORE(0);
    __syncthreads();

    for (int cg = 0; cg < NC; cg++) {
        const int cur = cg & 1;
        if (cg + 1 < NC) GLOAD(cg + 1);

#pragma unroll
        for (int ks = 0; ks < 2; ks++) {
            const int kb = ks * 16 + kq;
            uint32_t af[4][4], bf[4][2];
#pragma unroll
            for (int i = 0; i < 4; i++) {
                const __nv_bfloat16* ab = &As[cur][(wm * 64 + i * 16 + r) * LDS_ + kb];
                af[i][0] = *reinterpret_cast<const uint32_t*>(ab);
                af[i][1] = *reinterpret_cast<const uint32_t*>(ab + 8 * LDS_);
                af[i][2] = *reinterpret_cast<const uint32_t*>(ab + 8);
                af[i][3] = *reinterpret_cast<const uint32_t*>(ab + 8 * LDS_ + 8);
            }
#pragma unroll
            for (int j = 0; j < 4; j++) {
                const __nv_bfloat16* bb = &Bs[cur][(wn * 32 + j * 8 + r) * LDS_ + kb];
                bf[j][0] = *reinterpret_cast<const uint32_t*>(bb);
                bf[j][1] = *reinterpret_cast<const uint32_t*>(bb + 8);
            }
#pragma unroll
            for (int i = 0; i < 4; i++)
#pragma unroll
                for (int j = 0; j < 4; j++)
                    mma16816(acc[i][j], af[i], bf[j]);
        }

        if (cg + 1 < NC) SSTORE(cur ^ 1);
        __syncthreads();
    }

    // Epilogue: c0,c1 -> (row, col..col+1); c2,c3 -> (row+8, col..col+1)
#pragma unroll
    for (int i = 0; i < 4; i++) {
#pragma unroll
        for (int j = 0; j < 4; j++) {
            const int row = m0 + wm * 64 + i * 16 + r;
            const int col = n0 + wn * 32 + j * 8 + kq;
            const float b0 = bias[col], b1 = bias[col + 1];
            float2 o0 = {acc[i][j][0] + b0, acc[i][j][1] + b1};
            float2 o1 = {acc[i][j][2] + b0, acc[i][j][3] + b1};
            *reinterpret_cast<float2*>(C + (size_t)row * D_ + col)       = o0;
            *reinterpret_cast<float2*>(C + (size_t)(row + 8) * D_ + col) = o1;
        }
    }
#undef GLOAD
#undef SSTORE
}

// ---------------------------------------------------------------------------
// Flash attention (unchanged from R10 passing kernel).
// ---------------------------------------------------------------------------
#define SSTR 65
#define FLASH_SMEM ((4*64*SSTR + 4*64) * sizeof(float))

__global__ __launch_bounds__(256)
void flash_kernel(const float* __restrict__ Qg, const float* __restrict__ Kg,
                  const float* __restrict__ Vg, const float* __restrict__ dsg,
                  const float* __restrict__ betap, float* __restrict__ ctx)
{
    extern __shared__ float sm[];
    float* Qs     = sm;
    float* Ks     = Qs + 64*SSTR;
    float* Vs     = Ks + 64*SSTR;
    float* Ps     = Vs + 64*SSTR;
    float* m_s    = Ps + 64*SSTR;
    float* l_s    = m_s + 64;
    float* corr_s = l_s + 64;
    float* ds_s   = corr_s + 64;

    const int bh = blockIdx.y;
    const int b  = bh >> 4;
    const int h  = bh & 15;
    const int q0 = blockIdx.x * 64;
    const int tid = threadIdx.x;
    const int tx = tid & 15;
    const int ty = tid >> 4;

    const float* Qb = Qg + ((size_t)(b*S_ + q0)) * D_ + h*HD_;
    const float* Kb = Kg + ((size_t)b * S_) * D_ + h*HD_;
    const float* Vb = Vg + ((size_t)b * S_) * D_ + h*HD_;

    for (int idx = tid; idx < 4096; idx += 256) {
        int r = idx >> 6, c = idx & 63;
        Qs[r*SSTR + c] = Qb[(size_t)r * D_ + c];
    }
    if (tid < 64) { m_s[tid] = -1e30f; l_s[tid] = 0.f; }

    float O[4][4], dsacc[4];
#pragma unroll
    for (int i = 0; i < 4; i++) {
        dsacc[i] = 0.f;
#pragma unroll
        for (int j = 0; j < 4; j++) O[i][j] = 0.f;
    }

    for (int kt = 0; kt < S_; kt += 64) {
        __syncthreads();
        for (int idx = tid; idx < 4096; idx += 256) {
            int r = idx >> 6, c = idx & 63;
            Ks[r*SSTR + c] = Kb[(size_t)(kt + r) * D_ + c];
            Vs[r*SSTR + c] = Vb[(size_t)(kt + r) * D_ + c];
        }
        if (tid < 64) ds_s[tid] = dsg[b*S_ + kt + tid];
        __syncthreads();

        float s[4][4];
#pragma unroll
        for (int i = 0; i < 4; i++)
#pragma unroll
            for (int j = 0; j < 4; j++) s[i][j] = 0.f;

#pragma unroll
        for (int d = 0; d < 64; d++) {
            float a0 = Qs[(ty*4+0)*SSTR + d];
            float a1 = Qs[(ty*4+1)*SSTR + d];
            float a2 = Qs[(ty*4+2)*SSTR + d];
            float a3 = Qs[(ty*4+3)*SSTR + d];
            float b0 = Ks[(tx*4+0)*SSTR + d];
            float b1 = Ks[(tx*4+1)*SSTR + d];
            float b2 = Ks[(tx*4+2)*SSTR + d];
            float b3 = Ks[(tx*4+3)*SSTR + d];
            s[0][0] = fmaf(a0,b0,s[0][0]); s[0][1] = fmaf(a0,b1,s[0][1]);
            s[0][2] = fmaf(a0,b2,s[0][2]); s[0][3] = fmaf(a0,b3,s[0][3]);
            s[1][0] = fmaf(a1,b0,s[1][0]); s[1][1] = fmaf(a1,b1,s[1][1]);
            s[1][2] = fmaf(a1,b2,s[1][2]); s[1][3] = fmaf(a1,b3,s[1][3]);
            s[2][0] = fmaf(a2,b0,s[2][0]); s[2][1] = fmaf(a2,b1,s[2][1]);
            s[2][2] = fmaf(a2,b2,s[2][2]); s[2][3] = fmaf(a2,b3,s[2][3]);
            s[3][0] = fmaf(a3,b0,s[3][0]); s[3][1] = fmaf(a3,b1,s[3][1]);
            s[3][2] = fmaf(a3,b2,s[3][2]); s[3][3] = fmaf(a3,b3,s[3][3]);
        }
#pragma unroll
        for (int i = 0; i < 4; i++)
#pragma unroll
            for (int j = 0; j < 4; j++)
                Ps[(ty*4+i)*SSTR + tx*4 + j] = s[i][j] * 0.125f;
        __syncthreads();

        if (tid < 64) {
            const float* row = Ps + tid*SSTR;
            float tm = row[0];
            for (int k2 = 1; k2 < 64; k2++) tm = fmaxf(tm, row[k2]);
            float mo = m_s[tid];
            float mn = fmaxf(mo, tm);
            corr_s[tid] = __expf(mo - mn);
            m_s[tid] = mn;
        }
        __syncthreads();

#pragma unroll
        for (int i = 0; i < 4; i++) {
            float c = corr_s[ty*4 + i];
#pragma unroll
            for (int j = 0; j < 4; j++) O[i][j] *= c;
        }
        for (int idx = tid; idx < 4096; idx += 256) {
            int r = idx >> 6, c = idx & 63;
            Ps[r*SSTR + c] = __expf(Ps[r*SSTR + c] - m_s[r]);
        }
        __syncthreads();

        if (tid < 64) {
            const float* row = Ps + tid*SSTR;
            float rs = 0.f;
            for (int k2 = 0; k2 < 64; k2++) rs += row[k2];
            l_s[tid] = l_s[tid]*corr_s[tid] + rs;
        }

#pragma unroll
        for (int k2 = 0; k2 < 64; k2++) {
            float p0 = Ps[(ty*4+0)*SSTR + k2];
            float p1 = Ps[(ty*4+1)*SSTR + k2];
            float p2 = Ps[(ty*4+2)*SSTR + k2];
            float p3 = Ps[(ty*4+3)*SSTR + k2];
            float v0 = Vs[k2*SSTR + tx*4 + 0];
            float v1 = Vs[k2*SSTR + tx*4 + 1];
            float v2 = Vs[k2*SSTR + tx*4 + 2];
            float v3 = Vs[k2*SSTR + tx*4 + 3];
            float dw = ds_s[k2];
            O[0][0] = fmaf(p0,v0,O[0][0]); O[0][1] = fmaf(p0,v1,O[0][1]);
            O[0][2] = fmaf(p0,v2,O[0][2]); O[0][3] = fmaf(p0,v3,O[0][3]);
            O[1][0] = fmaf(p1,v0,O[1][0]); O[1][1] = fmaf(p1,v1,O[1][1]);
            O[1][2] = fmaf(p1,v2,O[1][2]); O[1][3] = fmaf(p1,v3,O[1][3]);
            O[2][0] = fmaf(p2,v0,O[2][0]); O[2][1] = fmaf(p2,v1,O[2][1]);
            O[2][2] = fmaf(p2,v2,O[2][2]); O[2][3] = fmaf(p2,v3,O[2][3]);
            O[3][0] = fmaf(p3,v0,O[3][0]); O[3][1] = fmaf(p3,v1,O[3][1]);
            O[3][2] = fmaf(p3,v2,O[3][2]); O[3][3] = fmaf(p3,v3,O[3][3]);
            dsacc[0] = fmaf(dw,v0,dsacc[0]); dsacc[1] = fmaf(dw,v1,dsacc[1]);
            dsacc[2] = fmaf(dw,v2,dsacc[2]); dsacc[3] = fmaf(dw,v3,dsacc[3]);
        }
    }
    __syncthreads();

    const float bv  = *betap;
    const float omb = 1.f - bv;
#pragma unroll
    for (int i = 0; i < 4; i++) {
        int r = ty*4 + i;
        float invl = 1.f / l_s[r];
        float4 o;
        o.x = omb * O[i][0] * invl + bv * dsacc[0];
        o.y = omb * O[i][1] * invl + bv * dsacc[1];
        o.z = omb * O[i][2] * invl + bv * dsacc[2];
        o.w = omb * O[i][3] * invl + bv * dsacc[3];
        *reinterpret_cast<float4*>(ctx + ((size_t)(b*S_ + q0 + r)) * D_ + h*HD_ + tx*4) = o;
    }
}

// ---------------------------------------------------------------------------
extern "C" void kernel_launch(void* const* d_in, const int* in_sizes, int n_in,
                              void* d_out, int out_size)
{
    (void)in_sizes; (void)n_in; (void)out_size;
    const float* x    = (const float*)d_in[0];
    const float* ds   = (const float*)d_in[1];
    const float* Wq   = (const float*)d_in[2];
    const float* bq   = (const float*)d_in[3];
    const float* Wk   = (const float*)d_in[4];
    const float* bk   = (const float*)d_in[5];
    const float* Wv   = (const float*)d_in[6];
    const float* bv   = (const float*)d_in[7];
    const float* Wo   = (const float*)d_in[8];
    const float* bo   = (const float*)d_in[9];
    const float* beta = (const float*)d_in[10];
    float* out = (float*)d_out;

    float *Qp, *Kp, *Vp, *Cp;
    __nv_bfloat16 *Xh, *Xl, *Ch, *Cl, *Wth, *Wtl;
    cudaGetSymbolAddress((void**)&Qp,  g_Q);
    cudaGetSymbolAddress((void**)&Kp,  g_K);
    cudaGetSymbolAddress((void**)&Vp,  g_V);
    cudaGetSymbolAddress((void**)&Cp,  g_ctx);
    cudaGetSymbolAddress((void**)&Xh,  g_Xh);
    cudaGetSymbolAddress((void**)&Xl,  g_Xl);
    cudaGetSymbolAddress((void**)&Ch,  g_Ch);
    cudaGetSymbolAddress((void**)&Cl,  g_Cl);
    cudaGetSymbolAddress((void**)&Wth, g_Wth);
    cudaGetSymbolAddress((void**)&Wtl, g_Wtl);

    cudaFuncSetAttribute(flash_kernel, cudaFuncAttributeMaxDynamicSharedMemorySize,
                         (int)FLASH_SMEM);

    const size_t WSZ = (size_t)D_ * D_;
    dim3 tgrid(32, 32), tblk(32, 8);
    dim3 ggrid(D_/128, M_/128);   // (8, 32)

    // Prepare bf16 split operands
    split_rows<<<4096, 256>>>(x, Xh, Xl);
    transpose_split<<<tgrid, tblk>>>(Wq, Wth + 0*WSZ, Wtl + 0*WSZ);
    transpose_split<<<tgrid, tblk>>>(Wk, Wth + 1*WSZ, Wtl + 1*WSZ);
    transpose_split<<<tgrid, tblk>>>(Wv, Wth + 2*WSZ, Wtl + 2*WSZ);
    transpose_split<<<tgrid, tblk>>>(Wo, Wth + 3*WSZ, Wtl + 3*WSZ);

    // Q/K/V projections on tensor cores (mma.sync / HMMA)
    gemm_mma<<<ggrid, 256>>>(Xh, Xl, Wth + 0*WSZ, Wtl + 0*WSZ, bq, Qp);
    gemm_mma<<<ggrid, 256>>>(Xh, Xl, Wth + 1*WSZ, Wtl + 1*WSZ, bk, Kp);
    gemm_mma<<<ggrid, 256>>>(Xh, Xl, Wth + 2*WSZ, Wtl + 2*WSZ, bv, Vp);

    // Attention
    flash_kernel<<<dim3(S_/64, B_*H_), 256, FLASH_SMEM>>>(Qp, Kp, Vp, ds, beta, Cp);

    // Output projection
    split_rows<<<4096, 256>>>(Cp, Ch, Cl);
    gemm_mma<<<ggrid, 256>>>(Ch, Cl, Wth + 3*WSZ, Wtl + 3*WSZ, bo, out);
}

// round 15
// speedup vs baseline: 1.7522x; 1.4361x over previous
#include <cuda_runtime.h>
#include <cuda_bf16.h>
#include <cstdint>

using bf16 = __nv_bfloat16;

#define B_  2
#define S_  2048
#define D_  1024
#define H_  16
#define HD_ 64
#define M_  (B_*S_)          // 4096 rows for all GEMMs

// ---------------------------------------------------------------------------
// Scratch (allocation-free rule: __device__ globals).
// ---------------------------------------------------------------------------
__device__ bf16 g_Xh[(size_t)M_*D_];      // x split hi
__device__ bf16 g_Xl[(size_t)M_*D_];      // x split lo
__device__ bf16 g_Qh[(size_t)M_*D_];      // Q/8 split hi   [row][h*64+d]
__device__ bf16 g_Ql[(size_t)M_*D_];
__device__ bf16 g_Kh[(size_t)M_*D_];      // K split hi     [row][h*64+d]
__device__ bf16 g_Kl[(size_t)M_*D_];
__device__ bf16 g_Vth[(size_t)B_*H_*HD_*S_];  // V^T split hi  [(bh*64+hd)][s]
__device__ bf16 g_Vtl[(size_t)B_*H_*HD_*S_];
__device__ bf16 g_Ch[(size_t)M_*D_];      // ctx split hi
__device__ bf16 g_Cl[(size_t)M_*D_];
__device__ bf16 g_Wth[4][(size_t)D_*D_];  // W^T hi ([n][k] K-major)
__device__ bf16 g_Wtl[4][(size_t)D_*D_];
__device__ float g_dsV[B_*H_*HD_];        // rank-1 docking term  [bh][hd]

// ---------------------------------------------------------------------------
// Small helpers
// ---------------------------------------------------------------------------
__device__ __forceinline__ uint32_t smem_u32(const void* p) {
    uint32_t a;
    asm("{ .reg .u64 t; cvta.to.shared.u64 t, %1; cvt.u32.u64 %0, t; }"
        : "=r"(a) : "l"(p));
    return a;
}

__device__ __forceinline__ uint32_t lds32(uint32_t a) {
    uint32_t d;
    asm volatile("ld.shared.b32 %0, [%1];" : "=r"(d) : "r"(a));
    return d;
}

#define CP_ASYNC16(dst, src) \
    asm volatile("cp.async.cg.shared.global [%0], [%1], 16;" \
                 :: "r"(dst), "l"(src) : "memory")
#define CP_COMMIT() asm volatile("cp.async.commit_group;" ::: "memory")
template <int N>
__device__ __forceinline__ void cp_wait() {
    asm volatile("cp.async.wait_group %0;" :: "n"(N) : "memory");
}

// Pack two fp32 into bf16x2 (lo = a) plus bf16x2 residual.
__device__ __forceinline__ void packsplit(float a, float b, uint32_t& hi, uint32_t& lo) {
    uint32_t h;
    asm("cvt.rn.bf16x2.f32 %0, %1, %2;" : "=r"(h) : "f"(b), "f"(a));
    float ah = __uint_as_float(h << 16);
    float bh = __uint_as_float(h & 0xFFFF0000u);
    asm("cvt.rn.bf16x2.f32 %0, %1, %2;" : "=r"(lo) : "f"(b - bh), "f"(a - ah));
    hi = h;
}

__device__ __forceinline__ void split1(float v, bf16& hi, bf16& lo) {
    hi = __float2bfloat16(v);
    lo = __float2bfloat16(v - __bfloat162float(hi));
}

// Fast exp on fma/alu pipes (no MUFU): exp(x)=2^(x*log2e), deg-6 poly on [0,1).
__device__ __forceinline__ float fexp(float x) {
    float t = x * 1.4426950408889634f;
    t = fmaxf(t, -126.0f);
    int   ei = __float2int_rd(t);
    float f  = t - (float)ei;
    float p = 1.5402333e-4f;
    p = fmaf(p, f, 1.3333558e-3f);
    p = fmaf(p, f, 9.6181291e-3f);
    p = fmaf(p, f, 5.5504109e-2f);
    p = fmaf(p, f, 2.4022651e-1f);
    p = fmaf(p, f, 6.9314718e-1f);
    p = fmaf(p, f, 1.0f);
    return p * __int_as_float((ei + 127) << 23);
}

__device__ __forceinline__ void mma16816(float* d, const uint32_t* a, const uint32_t* b)
{
    asm volatile(
        "mma.sync.aligned.m16n8k16.row.col.f32.bf16.bf16.f32 "
        "{%0,%1,%2,%3}, {%4,%5,%6,%7}, {%8,%9}, {%0,%1,%2,%3};"
        : "+f"(d[0]), "+f"(d[1]), "+f"(d[2]), "+f"(d[3])
        : "r"(a[0]), "r"(a[1]), "r"(a[2]), "r"(a[3]), "r"(b[0]), "r"(b[1]));
}

// ---------------------------------------------------------------------------
// Convert kernels
// ---------------------------------------------------------------------------
__global__ __launch_bounds__(256)
void split_rows(const float* __restrict__ X,
                bf16* __restrict__ Xh, bf16* __restrict__ Xl)
{
    size_t i = ((size_t)blockIdx.x * 256 + threadIdx.x) * 4;
    float4 v = *reinterpret_cast<const float4*>(X + i);
    float f[4] = {v.x, v.y, v.z, v.w};
    alignas(8) bf16 h[4];
    alignas(8) bf16 l[4];
#pragma unroll
    for (int j = 0; j < 4; j++) split1(f[j], h[j], l[j]);
    *reinterpret_cast<uint2*>(Xh + i) = *reinterpret_cast<const uint2*>(h);
    *reinterpret_cast<uint2*>(Xl + i) = *reinterpret_cast<const uint2*>(l);
}

// W [K][N] fp32 -> Wt_hi/lo [N][K] bf16
__global__ __launch_bounds__(256)
void transpose_split(const float* __restrict__ W,
                     bf16* __restrict__ Th, bf16* __restrict__ Tl)
{
    __shared__ float t[32][33];
    const int bx = blockIdx.x * 32;   // n base
    const int by = blockIdx.y * 32;   // k base
    const int tx = threadIdx.x, ty = threadIdx.y;
#pragma unroll
    for (int i = 0; i < 32; i += 8)
        t[ty + i][tx] = W[(size_t)(by + ty + i) * D_ + bx + tx];
    __syncthreads();
#pragma unroll
    for (int i = 0; i < 32; i += 8) {
        float v = t[tx][ty + i];
        size_t o = (size_t)(bx + ty + i) * D_ + by + tx;
        bf16 h, l; split1(v, h, l);
        Th[o] = h; Tl[o] = l;
    }
}

// ---------------------------------------------------------------------------
// mma.sync split-bf16 GEMM, CTA 128x128, BK=32, 8 warps. Epilogue variants:
//   Cf    != null : fp32 C = acc + bias
//   Chh   != null : bf16 hi/lo of (acc+bias)*scale, row-major [M][D]
//   VtH   != null : bf16 hi/lo of (acc+bias), TRANSPOSED head layout
//                   Vt[(b*16+h)*64+hd][s]
// ---------------------------------------------------------------------------
#define BK_   32
#define LDS_  40

__global__ __launch_bounds__(256)
void gemm_mma(const bf16* __restrict__ Ahi, const bf16* __restrict__ Alo,
              const bf16* __restrict__ Bhi, const bf16* __restrict__ Blo,
              const float* __restrict__ bias,
              float* __restrict__ Cf,
              bf16* __restrict__ Chh, bf16* __restrict__ Cll,
              bf16* __restrict__ VtH, bf16* __restrict__ VtL,
              float scale)
{
    __shared__ __align__(16) bf16 As[2][128 * LDS_];
    __shared__ __align__(16) bf16 Bs[2][128 * LDS_];

    const int tid  = threadIdx.x;
    const int lane = tid & 31, wid = tid >> 5;
    const int wm   = wid >> 2, wn = wid & 3;
    const int m0   = blockIdx.y * 128, n0 = blockIdx.x * 128;
    const int r    = lane >> 2;
    const int kq   = (lane & 3) * 2;
    const int lrow = tid >> 2, lq = tid & 3;

    float acc[4][4][4];
#pragma unroll
    for (int i = 0; i < 4; i++)
#pragma unroll
        for (int j = 0; j < 4; j++)
#pragma unroll
            for (int c = 0; c < 4; c++) acc[i][j][c] = 0.f;

    const int NC = 96;
    uint4 stA0, stA1, stB0, stB1;

#define GLOAD(cg) do {                                                         \
    int _seg = (cg) >> 5;                                                      \
    int _kc  = ((cg) & 31) * BK_;                                              \
    const bf16* _Ag = (_seg == 2 ? Alo : Ahi) + (size_t)m0 * D_ + _kc;         \
    const bf16* _Bg = (_seg == 1 ? Blo : Bhi) + (size_t)n0 * D_ + _kc;         \
    stA0 = *reinterpret_cast<const uint4*>(_Ag + (size_t)lrow * D_ + lq * 8);  \
    stA1 = *reinterpret_cast<const uint4*>(_Ag + (size_t)(64 + lrow) * D_ + lq * 8); \
    stB0 = *reinterpret_cast<const uint4*>(_Bg + (size_t)lrow * D_ + lq * 8);  \
    stB1 = *reinterpret_cast<const uint4*>(_Bg + (size_t)(64 + lrow) * D_ + lq * 8); \
} while (0)

#define SSTORE(b) do {                                                         \
    *reinterpret_cast<uint4*>(&As[b][lrow * LDS_ + lq * 8])        = stA0;     \
    *reinterpret_cast<uint4*>(&As[b][(64 + lrow) * LDS_ + lq * 8]) = stA1;     \
    *reinterpret_cast<uint4*>(&Bs[b][lrow * LDS_ + lq * 8])        = stB0;     \
    *reinterpret_cast<uint4*>(&Bs[b][(64 + lrow) * LDS_ + lq * 8]) = stB1;     \
} while (0)

    GLOAD(0);
    SSTORE(0);
    __syncthreads();

    for (int cg = 0; cg < NC; cg++) {
        const int cur = cg & 1;
        if (cg + 1 < NC) GLOAD(cg + 1);

#pragma unroll
        for (int ks = 0; ks < 2; ks++) {
            const int kb = ks * 16 + kq;
            uint32_t af[4][4], bf[4][2];
#pragma unroll
            for (int i = 0; i < 4; i++) {
                const bf16* ab = &As[cur][(wm * 64 + i * 16 + r) * LDS_ + kb];
                af[i][0] = *reinterpret_cast<const uint32_t*>(ab);
                af[i][1] = *reinterpret_cast<const uint32_t*>(ab + 8 * LDS_);
                af[i][2] = *reinterpret_cast<const uint32_t*>(ab + 8);
                af[i][3] = *reinterpret_cast<const uint32_t*>(ab + 8 * LDS_ + 8);
            }
#pragma unroll
            for (int j = 0; j < 4; j++) {
                const bf16* bb = &Bs[cur][(wn * 32 + j * 8 + r) * LDS_ + kb];
                bf[j][0] = *reinterpret_cast<const uint32_t*>(bb);
                bf[j][1] = *reinterpret_cast<const uint32_t*>(bb + 8);
            }
#pragma unroll
            for (int i = 0; i < 4; i++)
#pragma unroll
                for (int j = 0; j < 4; j++)
                    mma16816(acc[i][j], af[i], bf[j]);
        }

        if (cg + 1 < NC) SSTORE(cur ^ 1);
        __syncthreads();
    }

#pragma unroll
    for (int i = 0; i < 4; i++) {
#pragma unroll
        for (int j = 0; j < 4; j++) {
            const int row = m0 + wm * 64 + i * 16 + r;
            const int col = n0 + wn * 32 + j * 8 + kq;
            const float b0 = bias[col], b1 = bias[col + 1];
            float v0 = acc[i][j][0] + b0, v1 = acc[i][j][1] + b1;
            float v2 = acc[i][j][2] + b0, v3 = acc[i][j][3] + b1;
            if (Cf) {
                float2 o0 = {v0, v1}, o1 = {v2, v3};
                *reinterpret_cast<float2*>(Cf + (size_t)row * D_ + col)       = o0;
                *reinterpret_cast<float2*>(Cf + (size_t)(row + 8) * D_ + col) = o1;
            }
            if (Chh) {
                uint32_t h0, l0, h1, l1;
                packsplit(v0 * scale, v1 * scale, h0, l0);
                packsplit(v2 * scale, v3 * scale, h1, l1);
                *reinterpret_cast<uint32_t*>(Chh + (size_t)row * D_ + col)       = h0;
                *reinterpret_cast<uint32_t*>(Cll + (size_t)row * D_ + col)       = l0;
                *reinterpret_cast<uint32_t*>(Chh + (size_t)(row + 8) * D_ + col) = h1;
                *reinterpret_cast<uint32_t*>(Cll + (size_t)(row + 8) * D_ + col) = l1;
            }
            if (VtH) {
                // transposed head layout: Vt[(b*16+h)*64+hd][s]
#pragma unroll
                for (int e = 0; e < 4; e++) {
                    int rr = row + (e >> 1) * 8;
                    int cc = col + (e & 1);
                    float vv = (e == 0 ? v0 : e == 1 ? v1 : e == 2 ? v2 : v3);
                    int bb = rr >> 11, ss = rr & (S_ - 1);
                    int hh = cc >> 6,  hd = cc & 63;
                    size_t off = ((size_t)((bb << 4) + hh) * 64 + hd) * S_ + ss;
                    bf16 hv, lv; split1(vv, hv, lv);
                    VtH[off] = hv; VtL[off] = lv;
                }
            }
        }
    }
#undef GLOAD
#undef SSTORE
}

// ---------------------------------------------------------------------------
// Rank-1 docking term: dsV[bh][d] = sum_s ds[b][s] * V[b,h,s,d]
// ---------------------------------------------------------------------------
__global__ __launch_bounds__(256)
void dsv_kernel(const bf16* __restrict__ Vth, const bf16* __restrict__ Vtl,
                const float* __restrict__ ds, float* __restrict__ dsV)
{
    __shared__ float part[256];
    const int bh = blockIdx.x, b = bh >> 4;
    const int d = threadIdx.x & 63, ch = threadIdx.x >> 6;
    const bf16* rh = Vth + ((size_t)bh * 64 + d) * S_;
    const bf16* rl = Vtl + ((size_t)bh * 64 + d) * S_;
    const float* dsr = ds + b * S_;
    float acc = 0.f;
    for (int s = ch * 512; s < ch * 512 + 512; s++)
        acc += dsr[s] * (__bfloat162float(rh[s]) + __bfloat162float(rl[s]));
    part[threadIdx.x] = acc;
    __syncthreads();
    if (threadIdx.x < 64)
        dsV[bh * 64 + threadIdx.x] =
            part[threadIdx.x] + part[64 + threadIdx.x] +
            part[128 + threadIdx.x] + part[192 + threadIdx.x];
}

// ---------------------------------------------------------------------------
// Tensor-core flash attention, split-bf16, 128 q-rows per CTA, k-tiles of 64.
// S = Qh*Kh + Qh*Kl + Ql*Kh  (1/8 folded into Q); online softmax in regs;
// O = Ph*Vh + Ph*Vl + Pl*Vh.  Epilogue: (1-beta)*O/l + beta*dsV -> Ch/Cl.
// ---------------------------------------------------------------------------
#define FL_SK    144                 // smem row stride bytes (72 bf16)
#define FL_TILE  (64 * FL_SK)        // 9216
#define FL_STAGE (4 * FL_TILE)       // 36864 (Kh,Kl,Vth,Vtl)
#define FL_QH    (2 * FL_STAGE)      // 73728
#define FL_QL    (FL_QH + 128 * FL_SK)
#define FL_DS    (FL_QL + 128 * FL_SK)
#define FL_SMEM  (FL_DS + 256)       // 110848 B

__global__ __launch_bounds__(256)
void flash_mma(const bf16* __restrict__ Qh, const bf16* __restrict__ Ql,
               const bf16* __restrict__ Kh, const bf16* __restrict__ Kl,
               const bf16* __restrict__ Vth, const bf16* __restrict__ Vtl,
               const float* __restrict__ dsV, const float* __restrict__ betap,
               bf16* __restrict__ Ch, bf16* __restrict__ Cl)
{
    extern __shared__ char smem[];
    const uint32_t sb = smem_u32(smem);
    const int tid = threadIdx.x, lane = tid & 31, w = tid >> 5;
    const int bh = blockIdx.y, b = bh >> 4, h = bh & 15;
    const int q0 = blockIdx.x * 128;
    const int r  = lane >> 2, cq = lane & 3;
    const size_t rowbase = (size_t)(b * S_ + q0);

    const float bv  = *betap;
    const float omb = 1.f - bv;

    // ds term into smem
    if (tid < 64)
        *reinterpret_cast<float*>(smem + FL_DS + tid * 4) = dsV[bh * 64 + tid];

    // Q hi/lo -> smem (cp.async, one time)
    for (int cc = tid; cc < 2048; cc += 256) {
        int a = cc >> 10, row = (cc >> 3) & 127, seg = cc & 7;
        const bf16* src = (a ? Ql : Qh) + (rowbase + row) * D_ + h * HD_ + seg * 8;
        uint32_t dst = sb + (a ? FL_QL : FL_QH) + row * FL_SK + seg * 16;
        CP_ASYNC16(dst, src);
    }

    // K/V stage loader
    auto issue_stage = [&](int kt) {
        const uint32_t base = sb + (kt & 1) * FL_STAGE;
        for (int cc = tid; cc < 2048; cc += 256) {
            int tile = cc >> 9, row = (cc >> 3) & 63, seg = cc & 7;
            const bf16* src;
            if (tile < 2) {
                src = (tile ? Kl : Kh) + (size_t)(b * S_ + kt * 64 + row) * D_
                      + h * HD_ + seg * 8;
            } else {
                src = (tile == 2 ? Vth : Vtl) + ((size_t)bh * 64 + row) * S_
                      + kt * 64 + seg * 8;
            }
            CP_ASYNC16(base + tile * FL_TILE + row * FL_SK + seg * 16, src);
        }
    };

    issue_stage(0);
    CP_COMMIT();

    // Per-lane state
    float S[8][4], O[8][4];
    float m0 = -1e30f, m1 = -1e30f, l0 = 0.f, l1 = 0.f;
#pragma unroll
    for (int j = 0; j < 8; j++)
#pragma unroll
        for (int c = 0; c < 4; c++) O[j][c] = 0.f;

    const uint32_t qh_base = sb + FL_QH + (w * 16 + r) * FL_SK + cq * 4;
    const uint32_t ql_base = sb + FL_QL + (w * 16 + r) * FL_SK + cq * 4;

    for (int kt = 0; kt < 32; kt++) {
        if (kt + 1 < 32) { issue_stage(kt + 1); CP_COMMIT(); cp_wait<1>(); }
        else cp_wait<0>();
        __syncthreads();

        const uint32_t stg = sb + (kt & 1) * FL_STAGE;
        const uint32_t Kb  = stg,                Klb = stg + FL_TILE;
        const uint32_t Vhb = stg + 2 * FL_TILE,  Vlb = stg + 3 * FL_TILE;

        // ---- S = Q @ K^T (split) ----
#pragma unroll
        for (int j = 0; j < 8; j++)
#pragma unroll
            for (int c = 0; c < 4; c++) S[j][c] = 0.f;

#pragma unroll
        for (int t = 0; t < 4; t++) {
            uint32_t qh[4], ql[4];
            qh[0] = lds32(qh_base + t * 32);
            qh[1] = lds32(qh_base + t * 32 + 8 * FL_SK);
            qh[2] = lds32(qh_base + t * 32 + 16);
            qh[3] = lds32(qh_base + t * 32 + 8 * FL_SK + 16);
            ql[0] = lds32(ql_base + t * 32);
            ql[1] = lds32(ql_base + t * 32 + 8 * FL_SK);
            ql[2] = lds32(ql_base + t * 32 + 16);
            ql[3] = lds32(ql_base + t * 32 + 8 * FL_SK + 16);
#pragma unroll
            for (int j = 0; j < 8; j++) {
                const uint32_t ka = (8 * j + r) * FL_SK + t * 32 + cq * 4;
                uint32_t kh[2], kl[2];
                kh[0] = lds32(Kb + ka);  kh[1] = lds32(Kb + ka + 16);
                kl[0] = lds32(Klb + ka); kl[1] = lds32(Klb + ka + 16);
                mma16816(S[j], qh, kh);
                mma16816(S[j], qh, kl);
                mma16816(S[j], ql, kh);
            }
        }

        // ---- online softmax (rows r and r+8) ----
        float mx0 = S[0][0], mx1 = S[0][2];
#pragma unroll
        for (int j = 0; j < 8; j++) {
            mx0 = fmaxf(mx0, fmaxf(S[j][0], S[j][1]));
            mx1 = fmaxf(mx1, fmaxf(S[j][2], S[j][3]));
        }
        mx0 = fmaxf(mx0, __shfl_xor_sync(0xFFFFFFFFu, mx0, 1));
        mx0 = fmaxf(mx0, __shfl_xor_sync(0xFFFFFFFFu, mx0, 2));
        mx1 = fmaxf(mx1, __shfl_xor_sync(0xFFFFFFFFu, mx1, 1));
        mx1 = fmaxf(mx1, __shfl_xor_sync(0xFFFFFFFFu, mx1, 2));

        const float mn0 = fmaxf(m0, mx0), mn1 = fmaxf(m1, mx1);
        const float cr0 = fexp(m0 - mn0), cr1 = fexp(m1 - mn1);
        m0 = mn0; m1 = mn1;

        float ps0 = 0.f, ps1 = 0.f;
#pragma unroll
        for (int j = 0; j < 8; j++) {
            S[j][0] = fexp(S[j][0] - m0); ps0 += S[j][0];
            S[j][1] = fexp(S[j][1] - m0); ps0 += S[j][1];
            S[j][2] = fexp(S[j][2] - m1); ps1 += S[j][2];
            S[j][3] = fexp(S[j][3] - m1); ps1 += S[j][3];
        }
        ps0 += __shfl_xor_sync(0xFFFFFFFFu, ps0, 1);
        ps0 += __shfl_xor_sync(0xFFFFFFFFu, ps0, 2);
        ps1 += __shfl_xor_sync(0xFFFFFFFFu, ps1, 1);
        ps1 += __shfl_xor_sync(0xFFFFFFFFu, ps1, 2);
        l0 = fmaf(l0, cr0, ps0);
        l1 = fmaf(l1, cr1, ps1);

#pragma unroll
        for (int j = 0; j < 8; j++) {
            O[j][0] *= cr0; O[j][1] *= cr0;
            O[j][2] *= cr1; O[j][3] *= cr1;
        }

        // ---- O += P @ V (split); P frags straight from S regs ----
#pragma unroll
        for (int t = 0; t < 4; t++) {
            uint32_t ph[4], pl[4];
            packsplit(S[2*t][0],     S[2*t][1],     ph[0], pl[0]);
            packsplit(S[2*t][2],     S[2*t][3],     ph[1], pl[1]);
            packsplit(S[2*t + 1][0], S[2*t + 1][1], ph[2], pl[2]);
            packsplit(S[2*t + 1][2], S[2*t + 1][3], ph[3], pl[3]);
#pragma unroll
            for (int j = 0; j < 8; j++) {
                const uint32_t va = (8 * j + r) * FL_SK + t * 32 + cq * 4;
                uint32_t vh[2], vl[2];
                vh[0] = lds32(Vhb + va); vh[1] = lds32(Vhb + va + 16);
                vl[0] = lds32(Vlb + va); vl[1] = lds32(Vlb + va + 16);
                mma16816(O[j], ph, vh);
                mma16816(O[j], ph, vl);
                mma16816(O[j], pl, vh);
            }
        }
        __syncthreads();
    }

    // ---- epilogue ----
    const float* sds = reinterpret_cast<const float*>(smem + FL_DS);
    const float w0 = omb / l0, w1 = omb / l1;
    const size_t g0 = (rowbase + w * 16 + r) * D_ + h * HD_;
    const size_t g1 = g0 + (size_t)8 * D_;
#pragma unroll
    for (int j = 0; j < 8; j++) {
        const int c0 = 8 * j + 2 * cq;
        const float d0 = bv * sds[c0], d1 = bv * sds[c0 + 1];
        uint32_t h0, lo0, h1, lo1;
        packsplit(O[j][0] * w0 + d0, O[j][1] * w0 + d1, h0, lo0);
        packsplit(O[j][2] * w1 + d0, O[j][3] * w1 + d1, h1, lo1);
        *reinterpret_cast<uint32_t*>(Ch + g0 + c0) = h0;
        *reinterpret_cast<uint32_t*>(Cl + g0 + c0) = lo0;
        *reinterpret_cast<uint32_t*>(Ch + g1 + c0) = h1;
        *reinterpret_cast<uint32_t*>(Cl + g1 + c0) = lo1;
    }
}

// ---------------------------------------------------------------------------
extern "C" void kernel_launch(void* const* d_in, const int* in_sizes, int n_in,
                              void* d_out, int out_size)
{
    (void)in_sizes; (void)n_in; (void)out_size;
    const float* x    = (const float*)d_in[0];
    const float* ds   = (const float*)d_in[1];
    const float* Wq   = (const float*)d_in[2];
    const float* bq   = (const float*)d_in[3];
    const float* Wk   = (const float*)d_in[4];
    const float* bk   = (const float*)d_in[5];
    const float* Wv   = (const float*)d_in[6];
    const float* bv   = (const float*)d_in[7];
    const float* Wo   = (const float*)d_in[8];
    const float* bo   = (const float*)d_in[9];
    const float* beta = (const float*)d_in[10];
    float* out = (float*)d_out;

    bf16 *Xh, *Xl, *Qhp, *Qlp, *Khp, *Klp, *Vth, *Vtl, *Chp, *Clp, *Wth, *Wtl;
    float* dsVp;
    cudaGetSymbolAddress((void**)&Xh,   g_Xh);
    cudaGetSymbolAddress((void**)&Xl,   g_Xl);
    cudaGetSymbolAddress((void**)&Qhp,  g_Qh);
    cudaGetSymbolAddress((void**)&Qlp,  g_Ql);
    cudaGetSymbolAddress((void**)&Khp,  g_Kh);
    cudaGetSymbolAddress((void**)&Klp,  g_Kl);
    cudaGetSymbolAddress((void**)&Vth,  g_Vth);
    cudaGetSymbolAddress((void**)&Vtl,  g_Vtl);
    cudaGetSymbolAddress((void**)&Chp,  g_Ch);
    cudaGetSymbolAddress((void**)&Clp,  g_Cl);
    cudaGetSymbolAddress((void**)&Wth,  g_Wth);
    cudaGetSymbolAddress((void**)&Wtl,  g_Wtl);
    cudaGetSymbolAddress((void**)&dsVp, g_dsV);

    cudaFuncSetAttribute(flash_mma, cudaFuncAttributeMaxDynamicSharedMemorySize,
                         (int)FL_SMEM);

    const size_t WSZ = (size_t)D_ * D_;
    dim3 tgrid(32, 32), tblk(32, 8);
    dim3 ggrid(D_/128, M_/128);   // (8, 32)

    split_rows<<<4096, 256>>>(x, Xh, Xl);
    transpose_split<<<tgrid, tblk>>>(Wq, Wth + 0*WSZ, Wtl + 0*WSZ);
    transpose_split<<<tgrid, tblk>>>(Wk, Wth + 1*WSZ, Wtl + 1*WSZ);
    transpose_split<<<tgrid, tblk>>>(Wv, Wth + 2*WSZ, Wtl + 2*WSZ);
    transpose_split<<<tgrid, tblk>>>(Wo, Wth + 3*WSZ, Wtl + 3*WSZ);

    // Projections: Q scaled by 1/sqrt(HD)=1/8, emitted bf16 hi/lo only.
    gemm_mma<<<ggrid, 256>>>(Xh, Xl, Wth + 0*WSZ, Wtl + 0*WSZ, bq,
                             nullptr, Qhp, Qlp, nullptr, nullptr, 0.125f);
    gemm_mma<<<ggrid, 256>>>(Xh, Xl, Wth + 1*WSZ, Wtl + 1*WSZ, bk,
                             nullptr, Khp, Klp, nullptr, nullptr, 1.0f);
    gemm_mma<<<ggrid, 256>>>(Xh, Xl, Wth + 2*WSZ, Wtl + 2*WSZ, bv,
                             nullptr, nullptr, nullptr, Vth, Vtl, 1.0f);

    dsv_kernel<<<B_*H_, 256>>>(Vth, Vtl, ds, dsVp);

    flash_mma<<<dim3(S_/128, B_*H_), 256, FL_SMEM>>>(
        Qhp, Qlp, Khp, Klp, Vth, Vtl, dsVp, beta, Chp, Clp);

    gemm_mma<<<ggrid, 256>>>(Chp, Clp, Wth + 3*WSZ, Wtl + 3*WSZ, bo,
                             out, nullptr, nullptr, nullptr, nullptr, 1.0f);
}